// round 7
// baseline (speedup 1.0000x reference)
#include <cuda_runtime.h>
#include <math.h>

// Problem constants (fixed by the dataset)
#define NMAX   100000
#define CIN    64
#define COUT   64
#define KNB    16
#define DIN    67          // 3 + CIN
#define PTS    64          // points per block
#define THREADS 256

typedef unsigned long long u64;

// Scratch for per-node A = [coords, feats] @ W1 + b1  (25.6 MB)
__device__ float g_A[(size_t)NMAX * COUT];

// ---- packed f32x2 helpers (sm_100+) --------------------------------------
__device__ __forceinline__ u64 pack2(float lo, float hi) {
    u64 r; asm("mov.b64 %0, {%1, %2};" : "=l"(r) : "f"(lo), "f"(hi)); return r;
}
__device__ __forceinline__ void unpack2(u64 v, float& lo, float& hi) {
    asm("mov.b64 {%0, %1}, %2;" : "=f"(lo), "=f"(hi) : "l"(v));
}
__device__ __forceinline__ u64 fma2(u64 a, u64 b, u64 c) {
    u64 d; asm("fma.rn.f32x2 %0, %1, %2, %3;" : "=l"(d) : "l"(a), "l"(b), "l"(c));
    return d;
}
__device__ __forceinline__ u64 mul2(u64 a, u64 b) {
    u64 d; asm("mul.rn.f32x2 %0, %1, %2;" : "=l"(d) : "l"(a), "l"(b)); return d;
}
__device__ __forceinline__ u64 add2(u64 a, u64 b) {
    u64 d; asm("add.rn.f32x2 %0, %1, %2;" : "=l"(d) : "l"(a), "l"(b)); return d;
}
__device__ __forceinline__ u64 and2(u64 a, u64 b) {
    u64 d; asm("and.b64 %0, %1, %2;" : "=l"(d) : "l"(a), "l"(b)); return d;
}
__device__ __forceinline__ u64 dup2(float f) {
    unsigned u = __float_as_uint(f);
    return (u64)u | ((u64)u << 32);
}
__device__ __forceinline__ float rcpf(float x) {
    float r; asm("rcp.approx.ftz.f32 %0, %1;" : "=f"(r) : "f"(x)); return r;
}

// ---- packed GELU (2 values at once) ---------------------------------------
// gelu(x) = 0.5x + 0.5|x|*erf(|x|/sqrt2)
// erf via A&S 7.1.28: erf(t) = 1 - (1 + a1 t + ... + a6 t^6)^-16,  |eps|<=3e-7
// No EX2 needed; one RCP per value; rest packs as f32x2 on the fma pipe.
__device__ __forceinline__ u64 gelu2(u64 x) {
    u64 ax = and2(x, 0x7FFFFFFF7FFFFFFFULL);
    u64 t  = mul2(ax, dup2(0.70710678118654752440f));
    u64 p  = fma2(dup2(0.0000430638f), t, dup2(0.0002765672f));
    p = fma2(p, t, dup2(0.0001520143f));
    p = fma2(p, t, dup2(0.0092705272f));
    p = fma2(p, t, dup2(0.0422820123f));
    p = fma2(p, t, dup2(0.0705230784f));
    p = fma2(p, t, dup2(1.0f));
    float plo, phi; unpack2(p, plo, phi);
    u64 r = pack2(rcpf(plo), rcpf(phi));
    u64 r2  = mul2(r, r);
    u64 r4  = mul2(r2, r2);
    u64 r8  = mul2(r4, r4);
    u64 r16 = mul2(r8, r8);
    u64 E   = fma2(r16, dup2(-1.0f), dup2(1.0f));   // erf(t)
    u64 hax = mul2(ax, dup2(0.5f));
    u64 hx  = mul2(x,  dup2(0.5f));
    return fma2(hax, E, hx);
}

// ---------------------------------------------------------------------------
// Kernel 1: per-node precompute.
//   g_A[i]  = [coords_i, f_i] @ W1 + b1
//   out[i]  = f_i @ Ws + (b2 + bs)      (skip path; K2 accumulates on top)
// Dynamic smem: W1s[67*64] | Wss[64*64] | xsT[67][68]
// ---------------------------------------------------------------------------
#define K1_W1   0
#define K1_WS   4288
#define K1_XT   8384
#define K1_SMEM_BYTES ((8384 + 67 * 68) * 4)   // 51760

__global__ __launch_bounds__(THREADS, 3)
void compute_A_kernel(const float* __restrict__ coords,
                      const float* __restrict__ features,
                      const float* __restrict__ W1,
                      const float* __restrict__ b1,
                      const float* __restrict__ Ws,
                      const float* __restrict__ b2,
                      const float* __restrict__ bs,
                      float* __restrict__ out,
                      int N) {
    extern __shared__ float sm1[];
    float* W1s = sm1 + K1_W1;
    float* Wss = sm1 + K1_WS;
    float* xsT = sm1 + K1_XT;      // [j][point], stride 68

    const int t  = threadIdx.x;
    const int i0 = blockIdx.x * PTS;
    const int q  = t & 15;
    const int pg = t >> 4;

    {
        const float4* src = (const float4*)W1;
        float4* dst = (float4*)W1s;
        for (int e = t; e < (DIN * COUT) / 4; e += THREADS) dst[e] = src[e];
        const float4* ss = (const float4*)Ws;
        float4* ds = (float4*)Wss;
        for (int e = t; e < (CIN * COUT) / 4; e += THREADS) ds[e] = ss[e];
    }
    {
        int c  = t & 63;
        int p0 = t >> 6;
        #pragma unroll
        for (int rr = 0; rr < 16; ++rr) {
            int pt = p0 * 16 + rr;
            if (i0 + pt < N)
                xsT[(3 + c) * 68 + pt] = features[(size_t)(i0 + pt) * CIN + c];
        }
    }
    if (t < PTS * 3) {
        int pt = t / 3, d = t - pt * 3;
        if (i0 + pt < N) xsT[d * 68 + pt] = coords[(size_t)(i0 + pt) * 3 + d];
    }
    __syncthreads();

    // ---- A = x @ W1 + b1 ---------------------------------------------------
    {
        u64 accLo[4], accHi[4];
        float4 bb = ((const float4*)b1)[q];
        u64 blo = pack2(bb.x, bb.y), bhi = pack2(bb.z, bb.w);
        #pragma unroll
        for (int r = 0; r < 4; ++r) { accLo[r] = blo; accHi[r] = bhi; }

        #pragma unroll
        for (int j = 0; j < DIN; ++j) {
            float4 w = *(const float4*)(W1s + j * COUT + q * 4);
            u64 wlo = pack2(w.x, w.y), whi = pack2(w.z, w.w);
            float4 xv = *(const float4*)(xsT + j * 68 + pg * 4);
            u64 x0 = pack2(xv.x, xv.x);
            u64 x1 = pack2(xv.y, xv.y);
            u64 x2 = pack2(xv.z, xv.z);
            u64 x3 = pack2(xv.w, xv.w);
            accLo[0] = fma2(x0, wlo, accLo[0]);  accHi[0] = fma2(x0, whi, accHi[0]);
            accLo[1] = fma2(x1, wlo, accLo[1]);  accHi[1] = fma2(x1, whi, accHi[1]);
            accLo[2] = fma2(x2, wlo, accLo[2]);  accHi[2] = fma2(x2, whi, accHi[2]);
            accLo[3] = fma2(x3, wlo, accLo[3]);  accHi[3] = fma2(x3, whi, accHi[3]);
        }
        #pragma unroll
        for (int r = 0; r < 4; ++r) {
            int i = i0 + pg * 4 + r;
            if (i < N) {
                float o0, o1, o2, o3;
                unpack2(accLo[r], o0, o1);
                unpack2(accHi[r], o2, o3);
                *(float4*)(g_A + (size_t)i * COUT + q * 4) = make_float4(o0, o1, o2, o3);
            }
        }
    }

    // ---- skip = f @ Ws + (b2 + bs) -> out ----------------------------------
    {
        u64 accLo[4], accHi[4];
        float4 bb2 = ((const float4*)b2)[q];
        float4 bbs = ((const float4*)bs)[q];
        u64 blo = pack2(bb2.x + bbs.x, bb2.y + bbs.y);
        u64 bhi = pack2(bb2.z + bbs.z, bb2.w + bbs.w);
        #pragma unroll
        for (int r = 0; r < 4; ++r) { accLo[r] = blo; accHi[r] = bhi; }

        #pragma unroll
        for (int j = 0; j < CIN; ++j) {
            float4 w = *(const float4*)(Wss + j * COUT + q * 4);
            u64 wlo = pack2(w.x, w.y), whi = pack2(w.z, w.w);
            float4 xv = *(const float4*)(xsT + (3 + j) * 68 + pg * 4);
            u64 x0 = pack2(xv.x, xv.x);
            u64 x1 = pack2(xv.y, xv.y);
            u64 x2 = pack2(xv.z, xv.z);
            u64 x3 = pack2(xv.w, xv.w);
            accLo[0] = fma2(x0, wlo, accLo[0]);  accHi[0] = fma2(x0, whi, accHi[0]);
            accLo[1] = fma2(x1, wlo, accLo[1]);  accHi[1] = fma2(x1, whi, accHi[1]);
            accLo[2] = fma2(x2, wlo, accLo[2]);  accHi[2] = fma2(x2, whi, accHi[2]);
            accLo[3] = fma2(x3, wlo, accLo[3]);  accHi[3] = fma2(x3, whi, accHi[3]);
        }
        #pragma unroll
        for (int r = 0; r < 4; ++r) {
            int i = i0 + pg * 4 + r;
            if (i < N) {
                float o0, o1, o2, o3;
                unpack2(accLo[r], o0, o1);
                unpack2(accHi[r], o2, o3);
                *(float4*)(out + (size_t)i * COUT + q * 4) = make_float4(o0, o1, o2, o3);
            }
        }
    }
}

// ---------------------------------------------------------------------------
// Kernel 2: gather + GELU + mean + (out += Hbar @ W2), 64 points / block.
// Dynamic smem (floats): W2s[4096] hT[64*68] cs[192] | idxs[1024] (int)
// ---------------------------------------------------------------------------
#define SM_W2   0
#define SM_HT   4096
#define SM_CS   (4096 + 64 * 68)
#define SM_FLOATS (SM_CS + 192)
#define K2_SMEM_BYTES (SM_FLOATS * 4 + 1024 * 4)   // 38656

__global__ __launch_bounds__(THREADS, 4)
void fused_main_kernel(const float* __restrict__ coords,
                       const float* __restrict__ idx_unused,
                       const int* __restrict__ idx,
                       const float* __restrict__ W1,
                       const float* __restrict__ W2,
                       float* __restrict__ out,
                       int N) {
    extern __shared__ float sm2[];
    float* W2s = sm2 + SM_W2;
    float* hT  = sm2 + SM_HT;    // [channel][point], stride 68
    float* cs  = sm2 + SM_CS;    // [point][3]
    int*   idxs = (int*)(sm2 + SM_FLOATS);

    const int t  = threadIdx.x;
    const int i0 = blockIdx.x * PTS;
    const int q  = t & 15;
    const int pg = t >> 4;

    // ---- staging -----------------------------------------------------------
    {
        const float4* s2 = (const float4*)W2;
        float4* d2 = (float4*)W2s;
        for (int e = t; e < (COUT * COUT) / 4; e += THREADS) d2[e] = s2[e];
    }
    for (int e = t; e < PTS * KNB; e += THREADS) {
        int row = e >> 4;
        idxs[e] = (i0 + row < N) ? idx[(size_t)(i0 + row) * KNB + (e & 15)] : 0;
    }
    if (t < PTS * 3) {
        int pt = t / 3, d = t - pt * 3;
        if (i0 + pt < N) cs[pt * 3 + d] = coords[(size_t)(i0 + pt) * 3 + d];
    }
    __syncthreads();

    // ---- phase A: gather + packed GELU + mean ------------------------------
    {
        const float4* W1v = (const float4*)W1;
        float4 w0 = __ldg(W1v + 0 * 16 + q);
        float4 w1 = __ldg(W1v + 1 * 16 + q);
        float4 w2 = __ldg(W1v + 2 * 16 + q);

        #pragma unroll
        for (int r = 0; r < 4; ++r) {
            int pl = pg * 4 + r;
            int i  = i0 + pl;
            float h0 = 0.f, h1 = 0.f, h2 = 0.f, h3 = 0.f;
            if (i < N) {
                float cx = cs[pl * 3 + 0], cy = cs[pl * 3 + 1], cz = cs[pl * 3 + 2];
                float bx = -(cx * w0.x + cy * w1.x + cz * w2.x);
                float by = -(cx * w0.y + cy * w1.y + cz * w2.y);
                float bz = -(cx * w0.z + cy * w1.z + cz * w2.z);
                float bw = -(cx * w0.w + cy * w1.w + cz * w2.w);
                u64 bLo = pack2(bx, by), bHi = pack2(bz, bw);
                u64 sLo = 0, sHi = 0;    // bit pattern of (0.f,0.f)
                #pragma unroll
                for (int k = 0; k < KNB; ++k) {
                    int j = idxs[pl * KNB + k];
                    float4 a = *(const float4*)(g_A + (size_t)j * COUT + q * 4);
                    u64 xLo = add2(pack2(a.x, a.y), bLo);
                    u64 xHi = add2(pack2(a.z, a.w), bHi);
                    sLo = add2(sLo, gelu2(xLo));
                    sHi = add2(sHi, gelu2(xHi));
                }
                u64 inv = dup2(1.0f / (float)KNB);
                sLo = mul2(sLo, inv);
                sHi = mul2(sHi, inv);
                unpack2(sLo, h0, h1);
                unpack2(sHi, h2, h3);
            }
            hT[(q * 4 + 0) * 68 + pl] = h0;
            hT[(q * 4 + 1) * 68 + pl] = h1;
            hT[(q * 4 + 2) * 68 + pl] = h2;
            hT[(q * 4 + 3) * 68 + pl] = h3;
        }
    }
    __syncthreads();

    // ---- phase B: out += Hbar @ W2 (acc init = skip written by K1) ---------
    u64 accLo[4], accHi[4];
    #pragma unroll
    for (int r = 0; r < 4; ++r) {
        int i = i0 + pg * 4 + r;
        if (i < N) {
            float4 o = *(const float4*)(out + (size_t)i * COUT + q * 4);
            accLo[r] = pack2(o.x, o.y);
            accHi[r] = pack2(o.z, o.w);
        } else {
            accLo[r] = 0; accHi[r] = 0;
        }
    }

    #pragma unroll 8
    for (int j = 0; j < COUT; ++j) {
        float4 wv2 = *(const float4*)(W2s + j * COUT + q * 4);
        u64 w2lo = pack2(wv2.x, wv2.y), w2hi = pack2(wv2.z, wv2.w);
        float4 h4 = *(const float4*)(hT + j * 68 + pg * 4);

        u64 hd;
        hd = pack2(h4.x, h4.x);
        accLo[0] = fma2(hd, w2lo, accLo[0]);  accHi[0] = fma2(hd, w2hi, accHi[0]);
        hd = pack2(h4.y, h4.y);
        accLo[1] = fma2(hd, w2lo, accLo[1]);  accHi[1] = fma2(hd, w2hi, accHi[1]);
        hd = pack2(h4.z, h4.z);
        accLo[2] = fma2(hd, w2lo, accLo[2]);  accHi[2] = fma2(hd, w2hi, accHi[2]);
        hd = pack2(h4.w, h4.w);
        accLo[3] = fma2(hd, w2lo, accLo[3]);  accHi[3] = fma2(hd, w2hi, accHi[3]);
    }

    #pragma unroll
    for (int r = 0; r < 4; ++r) {
        int i = i0 + pg * 4 + r;
        if (i < N) {
            float o0, o1, o2, o3;
            unpack2(accLo[r], o0, o1);
            unpack2(accHi[r], o2, o3);
            *(float4*)(out + (size_t)i * COUT + q * 4) = make_float4(o0, o1, o2, o3);
        }
    }
}

// ---------------------------------------------------------------------------
// Launch
// ---------------------------------------------------------------------------
extern "C" void kernel_launch(void* const* d_in, const int* in_sizes, int n_in,
                              void* d_out, int out_size) {
    const float* coords   = (const float*)d_in[0];
    const float* features = (const float*)d_in[1];
    const int*   idx      = (const int*)d_in[2];
    const float* W1       = (const float*)d_in[3];
    const float* b1       = (const float*)d_in[4];
    const float* W2       = (const float*)d_in[5];
    const float* b2       = (const float*)d_in[6];
    const float* Ws       = (const float*)d_in[7];
    const float* bs       = (const float*)d_in[8];
    float*       out      = (float*)d_out;

    const int N = in_sizes[0] / 3;
    const int blocks = (N + PTS - 1) / PTS;

    static int attr_done = 0;
    if (!attr_done) {
        cudaFuncSetAttribute(compute_A_kernel,
                             cudaFuncAttributeMaxDynamicSharedMemorySize,
                             K1_SMEM_BYTES);
        cudaFuncSetAttribute(fused_main_kernel,
                             cudaFuncAttributeMaxDynamicSharedMemorySize,
                             K2_SMEM_BYTES);
        attr_done = 1;
    }

    compute_A_kernel<<<blocks, THREADS, K1_SMEM_BYTES>>>(coords, features, W1,
                                                         b1, Ws, b2, bs, out, N);
    fused_main_kernel<<<blocks, THREADS, K2_SMEM_BYTES>>>(coords, nullptr, idx,
                                                          W1, W2, out, N);
}

// round 9
// speedup vs baseline: 1.4364x; 1.4364x over previous
#include <cuda_runtime.h>
#include <math.h>

// Problem constants (fixed by the dataset)
#define NMAX   100000
#define CIN    64
#define COUT   64
#define KNB    16
#define DIN    67          // 3 + CIN
#define PTS    64          // points per block
#define THREADS 256

typedef unsigned long long u64;

// Scratch for per-node A = [coords, feats] @ W1 + b1  (25.6 MB)
__device__ float g_A[(size_t)NMAX * COUT];

// ---- packed f32x2 helpers (sm_100+) --------------------------------------
__device__ __forceinline__ u64 pack2(float lo, float hi) {
    u64 r; asm("mov.b64 %0, {%1, %2};" : "=l"(r) : "f"(lo), "f"(hi)); return r;
}
__device__ __forceinline__ void unpack2(u64 v, float& lo, float& hi) {
    asm("mov.b64 {%0, %1}, %2;" : "=f"(lo), "=f"(hi) : "l"(v));
}
__device__ __forceinline__ u64 fma2(u64 a, u64 b, u64 c) {
    u64 d; asm("fma.rn.f32x2 %0, %1, %2, %3;" : "=l"(d) : "l"(a), "l"(b), "l"(c));
    return d;
}
__device__ __forceinline__ u64 mul2(u64 a, u64 b) {
    u64 d; asm("mul.rn.f32x2 %0, %1, %2;" : "=l"(d) : "l"(a), "l"(b)); return d;
}
__device__ __forceinline__ u64 add2(u64 a, u64 b) {
    u64 d; asm("add.rn.f32x2 %0, %1, %2;" : "=l"(d) : "l"(a), "l"(b)); return d;
}
__device__ __forceinline__ u64 and2(u64 a, u64 b) {
    u64 d; asm("and.b64 %0, %1, %2;" : "=l"(d) : "l"(a), "l"(b)); return d;
}
__device__ __forceinline__ u64 dup2(float f) {
    unsigned u = __float_as_uint(f);
    return (u64)u | ((u64)u << 32);
}
__device__ __forceinline__ float rcpf(float x) {
    float r; asm("rcp.approx.ftz.f32 %0, %1;" : "=f"(r) : "f"(x)); return r;
}

// ---- packed GELU (2 values at once) ---------------------------------------
// gelu(x) = 0.5x + 0.5|x|*erf(|x|/sqrt2)
// erf via A&S 7.1.28: erf(t) = 1 - (1 + a1 t + ... + a6 t^6)^-16,  |eps|<=3e-7
__device__ __forceinline__ u64 gelu2(u64 x) {
    u64 ax = and2(x, 0x7FFFFFFF7FFFFFFFULL);
    u64 t  = mul2(ax, dup2(0.70710678118654752440f));
    u64 p  = fma2(dup2(0.0000430638f), t, dup2(0.0002765672f));
    p = fma2(p, t, dup2(0.0001520143f));
    p = fma2(p, t, dup2(0.0092705272f));
    p = fma2(p, t, dup2(0.0422820123f));
    p = fma2(p, t, dup2(0.0705230784f));
    p = fma2(p, t, dup2(1.0f));
    float plo, phi; unpack2(p, plo, phi);
    u64 r = pack2(rcpf(plo), rcpf(phi));
    u64 r2  = mul2(r, r);
    u64 r4  = mul2(r2, r2);
    u64 r8  = mul2(r4, r4);
    u64 r16 = mul2(r8, r8);
    u64 E   = fma2(r16, dup2(-1.0f), dup2(1.0f));   // erf(t)
    u64 hax = mul2(ax, dup2(0.5f));
    u64 hx  = mul2(x,  dup2(0.5f));
    return fma2(hax, E, hx);
}

// ---------------------------------------------------------------------------
// Kernel 1a: A[i][c] = [coords_i, feat_i] @ W1 + b1    (R6-proven structure)
// ---------------------------------------------------------------------------
__global__ __launch_bounds__(THREADS, 4)
void compute_A_kernel(const float* __restrict__ coords,
                      const float* __restrict__ features,
                      const float* __restrict__ W1,
                      const float* __restrict__ b1,
                      int N) {
    __shared__ float W1s[DIN * COUT];   // [j][c] flat
    __shared__ float xsT[DIN][68];      // [j][point], padded

    const int t  = threadIdx.x;
    const int i0 = blockIdx.x * PTS;
    const int q  = t & 15;
    const int pg = t >> 4;

    {
        const float4* src = (const float4*)W1;
        float4* dst = (float4*)W1s;
        for (int e = t; e < (DIN * COUT) / 4; e += THREADS) dst[e] = src[e];
    }
    {
        int c  = t & 63;
        int p0 = t >> 6;
        #pragma unroll
        for (int rr = 0; rr < 16; ++rr) {
            int pt = p0 * 16 + rr;
            if (i0 + pt < N)
                xsT[3 + c][pt] = features[(size_t)(i0 + pt) * CIN + c];
        }
    }
    if (t < PTS * 3) {
        int pt = t / 3, d = t - pt * 3;
        if (i0 + pt < N) xsT[d][pt] = coords[(size_t)(i0 + pt) * 3 + d];
    }
    __syncthreads();

    u64 accLo[4], accHi[4];
    {
        float4 bb = ((const float4*)b1)[q];
        u64 blo = pack2(bb.x, bb.y), bhi = pack2(bb.z, bb.w);
        #pragma unroll
        for (int r = 0; r < 4; ++r) { accLo[r] = blo; accHi[r] = bhi; }
    }

    #pragma unroll
    for (int j = 0; j < DIN; ++j) {
        float4 w = *(const float4*)(W1s + j * COUT + q * 4);
        u64 wlo = pack2(w.x, w.y), whi = pack2(w.z, w.w);
        float4 xv = *(const float4*)(&xsT[j][pg * 4]);
        u64 x0 = pack2(xv.x, xv.x);
        u64 x1 = pack2(xv.y, xv.y);
        u64 x2 = pack2(xv.z, xv.z);
        u64 x3 = pack2(xv.w, xv.w);
        accLo[0] = fma2(x0, wlo, accLo[0]);  accHi[0] = fma2(x0, whi, accHi[0]);
        accLo[1] = fma2(x1, wlo, accLo[1]);  accHi[1] = fma2(x1, whi, accHi[1]);
        accLo[2] = fma2(x2, wlo, accLo[2]);  accHi[2] = fma2(x2, whi, accHi[2]);
        accLo[3] = fma2(x3, wlo, accLo[3]);  accHi[3] = fma2(x3, whi, accHi[3]);
    }

    #pragma unroll
    for (int r = 0; r < 4; ++r) {
        int i = i0 + pg * 4 + r;
        if (i < N) {
            float o0, o1, o2, o3;
            unpack2(accLo[r], o0, o1);
            unpack2(accHi[r], o2, o3);
            *(float4*)(g_A + (size_t)i * COUT + q * 4) = make_float4(o0, o1, o2, o3);
        }
    }
}

// ---------------------------------------------------------------------------
// Kernel 1b: skip path   out[i] = f_i @ Ws + (b2 + bs)
// Same tiling as K1a; K2 accumulates Hbar@W2 on top of this.
// ---------------------------------------------------------------------------
__global__ __launch_bounds__(THREADS, 4)
void skip_kernel(const float* __restrict__ features,
                 const float* __restrict__ Ws,
                 const float* __restrict__ b2,
                 const float* __restrict__ bs,
                 float* __restrict__ out,
                 int N) {
    __shared__ float Wss[CIN * COUT];   // 16 KB
    __shared__ float fsT[CIN][68];      // 17.4 KB

    const int t  = threadIdx.x;
    const int i0 = blockIdx.x * PTS;
    const int q  = t & 15;
    const int pg = t >> 4;

    {
        const float4* ss = (const float4*)Ws;
        float4* ds = (float4*)Wss;
        for (int e = t; e < (CIN * COUT) / 4; e += THREADS) ds[e] = ss[e];
    }
    {
        int c  = t & 63;
        int p0 = t >> 6;
        #pragma unroll
        for (int rr = 0; rr < 16; ++rr) {
            int pt = p0 * 16 + rr;
            if (i0 + pt < N)
                fsT[c][pt] = features[(size_t)(i0 + pt) * CIN + c];
        }
    }
    __syncthreads();

    u64 accLo[4], accHi[4];
    {
        float4 bb2 = ((const float4*)b2)[q];
        float4 bbs = ((const float4*)bs)[q];
        u64 blo = pack2(bb2.x + bbs.x, bb2.y + bbs.y);
        u64 bhi = pack2(bb2.z + bbs.z, bb2.w + bbs.w);
        #pragma unroll
        for (int r = 0; r < 4; ++r) { accLo[r] = blo; accHi[r] = bhi; }
    }

    #pragma unroll
    for (int j = 0; j < CIN; ++j) {
        float4 w = *(const float4*)(Wss + j * COUT + q * 4);
        u64 wlo = pack2(w.x, w.y), whi = pack2(w.z, w.w);
        float4 xv = *(const float4*)(&fsT[j][pg * 4]);
        u64 x0 = pack2(xv.x, xv.x);
        u64 x1 = pack2(xv.y, xv.y);
        u64 x2 = pack2(xv.z, xv.z);
        u64 x3 = pack2(xv.w, xv.w);
        accLo[0] = fma2(x0, wlo, accLo[0]);  accHi[0] = fma2(x0, whi, accHi[0]);
        accLo[1] = fma2(x1, wlo, accLo[1]);  accHi[1] = fma2(x1, whi, accHi[1]);
        accLo[2] = fma2(x2, wlo, accLo[2]);  accHi[2] = fma2(x2, whi, accHi[2]);
        accLo[3] = fma2(x3, wlo, accLo[3]);  accHi[3] = fma2(x3, whi, accHi[3]);
    }

    #pragma unroll
    for (int r = 0; r < 4; ++r) {
        int i = i0 + pg * 4 + r;
        if (i < N) {
            float o0, o1, o2, o3;
            unpack2(accLo[r], o0, o1);
            unpack2(accHi[r], o2, o3);
            *(float4*)(out + (size_t)i * COUT + q * 4) = make_float4(o0, o1, o2, o3);
        }
    }
}

// ---------------------------------------------------------------------------
// Kernel 2: gather + GELU + mean + (out += Hbar @ W2), 64 points / block.
// Dynamic smem (floats): W2s[4096] hT[64*68] cs[192] | idxs[1024] (int)
// ---------------------------------------------------------------------------
#define SM_W2   0
#define SM_HT   4096
#define SM_CS   (4096 + 64 * 68)
#define SM_FLOATS (SM_CS + 192)
#define K2_SMEM_BYTES (SM_FLOATS * 4 + 1024 * 4)   // 38656

__global__ __launch_bounds__(THREADS, 4)
void fused_main_kernel(const float* __restrict__ coords,
                       const int* __restrict__ idx,
                       const float* __restrict__ W1,
                       const float* __restrict__ W2,
                       float* __restrict__ out,
                       int N) {
    extern __shared__ float sm2[];
    float* W2s = sm2 + SM_W2;
    float* hT  = sm2 + SM_HT;    // [channel][point], stride 68
    float* cs  = sm2 + SM_CS;    // [point][3]
    int*   idxs = (int*)(sm2 + SM_FLOATS);

    const int t  = threadIdx.x;
    const int i0 = blockIdx.x * PTS;
    const int q  = t & 15;
    const int pg = t >> 4;

    // ---- staging -----------------------------------------------------------
    {
        const float4* s2 = (const float4*)W2;
        float4* d2 = (float4*)W2s;
        for (int e = t; e < (COUT * COUT) / 4; e += THREADS) d2[e] = s2[e];
    }
    for (int e = t; e < PTS * KNB; e += THREADS) {
        int row = e >> 4;
        idxs[e] = (i0 + row < N) ? idx[(size_t)(i0 + row) * KNB + (e & 15)] : 0;
    }
    if (t < PTS * 3) {
        int pt = t / 3, d = t - pt * 3;
        if (i0 + pt < N) cs[pt * 3 + d] = coords[(size_t)(i0 + pt) * 3 + d];
    }
    __syncthreads();

    // ---- phase A: gather + packed GELU + mean ------------------------------
    {
        const float4* W1v = (const float4*)W1;
        float4 w0 = __ldg(W1v + 0 * 16 + q);
        float4 w1 = __ldg(W1v + 1 * 16 + q);
        float4 w2 = __ldg(W1v + 2 * 16 + q);

        #pragma unroll
        for (int r = 0; r < 4; ++r) {
            int pl = pg * 4 + r;
            int i  = i0 + pl;
            float h0 = 0.f, h1 = 0.f, h2 = 0.f, h3 = 0.f;
            if (i < N) {
                float cx = cs[pl * 3 + 0], cy = cs[pl * 3 + 1], cz = cs[pl * 3 + 2];
                float bx = -(cx * w0.x + cy * w1.x + cz * w2.x);
                float by = -(cx * w0.y + cy * w1.y + cz * w2.y);
                float bz = -(cx * w0.z + cy * w1.z + cz * w2.z);
                float bw = -(cx * w0.w + cy * w1.w + cz * w2.w);
                u64 bLo = pack2(bx, by), bHi = pack2(bz, bw);
                u64 sLo = 0, sHi = 0;    // bit pattern of (0.f,0.f)
                #pragma unroll
                for (int k = 0; k < KNB; ++k) {
                    int j = idxs[pl * KNB + k];
                    float4 a = *(const float4*)(g_A + (size_t)j * COUT + q * 4);
                    u64 xLo = add2(pack2(a.x, a.y), bLo);
                    u64 xHi = add2(pack2(a.z, a.w), bHi);
                    sLo = add2(sLo, gelu2(xLo));
                    sHi = add2(sHi, gelu2(xHi));
                }
                u64 inv = dup2(1.0f / (float)KNB);
                sLo = mul2(sLo, inv);
                sHi = mul2(sHi, inv);
                unpack2(sLo, h0, h1);
                unpack2(sHi, h2, h3);
            }
            hT[(q * 4 + 0) * 68 + pl] = h0;
            hT[(q * 4 + 1) * 68 + pl] = h1;
            hT[(q * 4 + 2) * 68 + pl] = h2;
            hT[(q * 4 + 3) * 68 + pl] = h3;
        }
    }
    __syncthreads();

    // ---- phase B: out += Hbar @ W2 (acc init = skip written by K1b) --------
    u64 accLo[4], accHi[4];
    #pragma unroll
    for (int r = 0; r < 4; ++r) {
        int i = i0 + pg * 4 + r;
        if (i < N) {
            float4 o = *(const float4*)(out + (size_t)i * COUT + q * 4);
            accLo[r] = pack2(o.x, o.y);
            accHi[r] = pack2(o.z, o.w);
        } else {
            accLo[r] = 0; accHi[r] = 0;
        }
    }

    #pragma unroll 8
    for (int j = 0; j < COUT; ++j) {
        float4 wv2 = *(const float4*)(W2s + j * COUT + q * 4);
        u64 w2lo = pack2(wv2.x, wv2.y), w2hi = pack2(wv2.z, wv2.w);
        float4 h4 = *(const float4*)(hT + j * 68 + pg * 4);

        u64 hd;
        hd = pack2(h4.x, h4.x);
        accLo[0] = fma2(hd, w2lo, accLo[0]);  accHi[0] = fma2(hd, w2hi, accHi[0]);
        hd = pack2(h4.y, h4.y);
        accLo[1] = fma2(hd, w2lo, accLo[1]);  accHi[1] = fma2(hd, w2hi, accHi[1]);
        hd = pack2(h4.z, h4.z);
        accLo[2] = fma2(hd, w2lo, accLo[2]);  accHi[2] = fma2(hd, w2hi, accHi[2]);
        hd = pack2(h4.w, h4.w);
        accLo[3] = fma2(hd, w2lo, accLo[3]);  accHi[3] = fma2(hd, w2hi, accHi[3]);
    }

    #pragma unroll
    for (int r = 0; r < 4; ++r) {
        int i = i0 + pg * 4 + r;
        if (i < N) {
            float o0, o1, o2, o3;
            unpack2(accLo[r], o0, o1);
            unpack2(accHi[r], o2, o3);
            *(float4*)(out + (size_t)i * COUT + q * 4) = make_float4(o0, o1, o2, o3);
        }
    }
}

// ---------------------------------------------------------------------------
// Launch
// ---------------------------------------------------------------------------
extern "C" void kernel_launch(void* const* d_in, const int* in_sizes, int n_in,
                              void* d_out, int out_size) {
    const float* coords   = (const float*)d_in[0];
    const float* features = (const float*)d_in[1];
    const int*   idx      = (const int*)d_in[2];
    const float* W1       = (const float*)d_in[3];
    const float* b1       = (const float*)d_in[4];
    const float* W2       = (const float*)d_in[5];
    const float* b2       = (const float*)d_in[6];
    const float* Ws       = (const float*)d_in[7];
    const float* bs       = (const float*)d_in[8];
    float*       out      = (float*)d_out;

    const int N = in_sizes[0] / 3;
    const int blocks = (N + PTS - 1) / PTS;

    static int attr_done = 0;
    if (!attr_done) {
        cudaFuncSetAttribute(fused_main_kernel,
                             cudaFuncAttributeMaxDynamicSharedMemorySize,
                             K2_SMEM_BYTES);
        attr_done = 1;
    }

    compute_A_kernel<<<blocks, THREADS>>>(coords, features, W1, b1, N);
    skip_kernel<<<blocks, THREADS>>>(features, Ws, b2, bs, out, N);
    fused_main_kernel<<<blocks, THREADS, K2_SMEM_BYTES>>>(coords, idx, W1, W2,
                                                          out, N);
}

// round 11
// speedup vs baseline: 1.5053x; 1.0480x over previous
#include <cuda_runtime.h>
#include <math.h>

// Problem constants (fixed by the dataset)
#define NMAX   100000
#define CIN    64
#define COUT   64
#define KNB    16
#define DIN    67          // 3 + CIN
#define PTS    64          // points per block (K1 kernels)
#define PTS2   32          // points per block (K2)
#define THREADS 256

typedef unsigned long long u64;

// Scratch for per-node A = [coords, feats] @ W1 + b1  (25.6 MB)
__device__ float g_A[(size_t)NMAX * COUT];

// ---- packed f32x2 helpers (sm_100+) --------------------------------------
__device__ __forceinline__ u64 pack2(float lo, float hi) {
    u64 r; asm("mov.b64 %0, {%1, %2};" : "=l"(r) : "f"(lo), "f"(hi)); return r;
}
__device__ __forceinline__ void unpack2(u64 v, float& lo, float& hi) {
    asm("mov.b64 {%0, %1}, %2;" : "=f"(lo), "=f"(hi) : "l"(v));
}
__device__ __forceinline__ u64 fma2(u64 a, u64 b, u64 c) {
    u64 d; asm("fma.rn.f32x2 %0, %1, %2, %3;" : "=l"(d) : "l"(a), "l"(b), "l"(c));
    return d;
}
__device__ __forceinline__ u64 mul2(u64 a, u64 b) {
    u64 d; asm("mul.rn.f32x2 %0, %1, %2;" : "=l"(d) : "l"(a), "l"(b)); return d;
}
__device__ __forceinline__ u64 add2(u64 a, u64 b) {
    u64 d; asm("add.rn.f32x2 %0, %1, %2;" : "=l"(d) : "l"(a), "l"(b)); return d;
}
__device__ __forceinline__ u64 and2(u64 a, u64 b) {
    u64 d; asm("and.b64 %0, %1, %2;" : "=l"(d) : "l"(a), "l"(b)); return d;
}
__device__ __forceinline__ u64 dup2(float f) {
    unsigned u = __float_as_uint(f);
    return (u64)u | ((u64)u << 32);
}
__device__ __forceinline__ float rcpf(float x) {
    float r; asm("rcp.approx.ftz.f32 %0, %1;" : "=f"(r) : "f"(x)); return r;
}

// ---- packed GELU accumulate (2 values) ------------------------------------
// Caller accumulates sx += x separately; here we accumulate s += |x| * 0.5*erf(|x|/sqrt2).
// erf via A&S 7.1.28 with coefficients pre-scaled by (1/sqrt2)^k so the
// polynomial runs on |x| directly:  erf(t) = 1 - P(|x|)^-16, |eps|<=3e-7.
__device__ __forceinline__ u64 gelu_acc2(u64 s, u64 x) {
    u64 ax = and2(x, 0x7FFFFFFF7FFFFFFFULL);
    u64 p  = fma2(dup2(0.0000053830f), ax, dup2(0.0000488909f));
    p = fma2(p, ax, dup2(0.0000380036f));
    p = fma2(p, ax, dup2(0.0032776424f));
    p = fma2(p, ax, dup2(0.0211410061f));
    p = fma2(p, ax, dup2(0.0498673400f));
    p = fma2(p, ax, dup2(1.0f));
    float plo, phi; unpack2(p, plo, phi);
    u64 r = pack2(rcpf(plo), rcpf(phi));
    u64 r2  = mul2(r, r);
    u64 r4  = mul2(r2, r2);
    u64 r8  = mul2(r4, r4);
    u64 r16 = mul2(r8, r8);
    u64 Eh  = fma2(r16, dup2(-0.5f), dup2(0.5f));   // 0.5 * erf
    return fma2(ax, Eh, s);
}

// ---------------------------------------------------------------------------
// Kernel 1a: A[i][c] = [coords_i, feat_i] @ W1 + b1    (proven structure)
// ---------------------------------------------------------------------------
__global__ __launch_bounds__(THREADS, 4)
void compute_A_kernel(const float* __restrict__ coords,
                      const float* __restrict__ features,
                      const float* __restrict__ W1,
                      const float* __restrict__ b1,
                      int N) {
    __shared__ float W1s[DIN * COUT];
    __shared__ float xsT[DIN][68];

    const int t  = threadIdx.x;
    const int i0 = blockIdx.x * PTS;
    const int q  = t & 15;
    const int pg = t >> 4;

    {
        const float4* src = (const float4*)W1;
        float4* dst = (float4*)W1s;
        for (int e = t; e < (DIN * COUT) / 4; e += THREADS) dst[e] = src[e];
    }
    {
        int c  = t & 63;
        int p0 = t >> 6;
        #pragma unroll
        for (int rr = 0; rr < 16; ++rr) {
            int pt = p0 * 16 + rr;
            if (i0 + pt < N)
                xsT[3 + c][pt] = features[(size_t)(i0 + pt) * CIN + c];
        }
    }
    if (t < PTS * 3) {
        int pt = t / 3, d = t - pt * 3;
        if (i0 + pt < N) xsT[d][pt] = coords[(size_t)(i0 + pt) * 3 + d];
    }
    __syncthreads();

    u64 accLo[4], accHi[4];
    {
        float4 bb = ((const float4*)b1)[q];
        u64 blo = pack2(bb.x, bb.y), bhi = pack2(bb.z, bb.w);
        #pragma unroll
        for (int r = 0; r < 4; ++r) { accLo[r] = blo; accHi[r] = bhi; }
    }

    #pragma unroll
    for (int j = 0; j < DIN; ++j) {
        float4 w = *(const float4*)(W1s + j * COUT + q * 4);
        u64 wlo = pack2(w.x, w.y), whi = pack2(w.z, w.w);
        float4 xv = *(const float4*)(&xsT[j][pg * 4]);
        u64 x0 = pack2(xv.x, xv.x);
        u64 x1 = pack2(xv.y, xv.y);
        u64 x2 = pack2(xv.z, xv.z);
        u64 x3 = pack2(xv.w, xv.w);
        accLo[0] = fma2(x0, wlo, accLo[0]);  accHi[0] = fma2(x0, whi, accHi[0]);
        accLo[1] = fma2(x1, wlo, accLo[1]);  accHi[1] = fma2(x1, whi, accHi[1]);
        accLo[2] = fma2(x2, wlo, accLo[2]);  accHi[2] = fma2(x2, whi, accHi[2]);
        accLo[3] = fma2(x3, wlo, accLo[3]);  accHi[3] = fma2(x3, whi, accHi[3]);
    }

    #pragma unroll
    for (int r = 0; r < 4; ++r) {
        int i = i0 + pg * 4 + r;
        if (i < N) {
            float o0, o1, o2, o3;
            unpack2(accLo[r], o0, o1);
            unpack2(accHi[r], o2, o3);
            *(float4*)(g_A + (size_t)i * COUT + q * 4) = make_float4(o0, o1, o2, o3);
        }
    }
}

// ---------------------------------------------------------------------------
// Kernel 1b: skip path   out[i] = f_i @ Ws + (b2 + bs)
// ---------------------------------------------------------------------------
__global__ __launch_bounds__(THREADS, 4)
void skip_kernel(const float* __restrict__ features,
                 const float* __restrict__ Ws,
                 const float* __restrict__ b2,
                 const float* __restrict__ bs,
                 float* __restrict__ out,
                 int N) {
    __shared__ float Wss[CIN * COUT];
    __shared__ float fsT[CIN][68];

    const int t  = threadIdx.x;
    const int i0 = blockIdx.x * PTS;
    const int q  = t & 15;
    const int pg = t >> 4;

    {
        const float4* ss = (const float4*)Ws;
        float4* ds = (float4*)Wss;
        for (int e = t; e < (CIN * COUT) / 4; e += THREADS) ds[e] = ss[e];
    }
    {
        int c  = t & 63;
        int p0 = t >> 6;
        #pragma unroll
        for (int rr = 0; rr < 16; ++rr) {
            int pt = p0 * 16 + rr;
            if (i0 + pt < N)
                fsT[c][pt] = features[(size_t)(i0 + pt) * CIN + c];
        }
    }
    __syncthreads();

    u64 accLo[4], accHi[4];
    {
        float4 bb2 = ((const float4*)b2)[q];
        float4 bbs = ((const float4*)bs)[q];
        u64 blo = pack2(bb2.x + bbs.x, bb2.y + bbs.y);
        u64 bhi = pack2(bb2.z + bbs.z, bb2.w + bbs.w);
        #pragma unroll
        for (int r = 0; r < 4; ++r) { accLo[r] = blo; accHi[r] = bhi; }
    }

    #pragma unroll
    for (int j = 0; j < CIN; ++j) {
        float4 w = *(const float4*)(Wss + j * COUT + q * 4);
        u64 wlo = pack2(w.x, w.y), whi = pack2(w.z, w.w);
        float4 xv = *(const float4*)(&fsT[j][pg * 4]);
        u64 x0 = pack2(xv.x, xv.x);
        u64 x1 = pack2(xv.y, xv.y);
        u64 x2 = pack2(xv.z, xv.z);
        u64 x3 = pack2(xv.w, xv.w);
        accLo[0] = fma2(x0, wlo, accLo[0]);  accHi[0] = fma2(x0, whi, accHi[0]);
        accLo[1] = fma2(x1, wlo, accLo[1]);  accHi[1] = fma2(x1, whi, accHi[1]);
        accLo[2] = fma2(x2, wlo, accLo[2]);  accHi[2] = fma2(x2, whi, accHi[2]);
        accLo[3] = fma2(x3, wlo, accLo[3]);  accHi[3] = fma2(x3, whi, accHi[3]);
    }

    #pragma unroll
    for (int r = 0; r < 4; ++r) {
        int i = i0 + pg * 4 + r;
        if (i < N) {
            float o0, o1, o2, o3;
            unpack2(accLo[r], o0, o1);
            unpack2(accHi[r], o2, o3);
            *(float4*)(out + (size_t)i * COUT + q * 4) = make_float4(o0, o1, o2, o3);
        }
    }
}

// ---------------------------------------------------------------------------
// Kernel 2: gather + GELU + mean + (out += Hbar @ W2), 32 points / block.
// Thread (pg 0..15, q 0..15): 2 points x 4 channels.  Static smem ~28 KB,
// targeting 5 CTAs/SM (62.5% occ) for gather-latency hiding.
// ---------------------------------------------------------------------------
__global__ __launch_bounds__(THREADS, 5)
void fused_main_kernel(const float* __restrict__ coords,
                       const int* __restrict__ idx,
                       const float* __restrict__ W1,
                       const float* __restrict__ W2,
                       float* __restrict__ out,
                       int N) {
    __shared__ float W2s[COUT * COUT];     // 16 KB
    __shared__ float hT[COUT * 36];        // [channel][point], stride 36: 9 KB
    __shared__ float cs[PTS2 * 3];
    __shared__ int   idxs[PTS2 * KNB];     // 2 KB

    const int t  = threadIdx.x;
    const int i0 = blockIdx.x * PTS2;
    const int q  = t & 15;
    const int pg = t >> 4;

    // ---- staging -----------------------------------------------------------
    {
        const float4* s2 = (const float4*)W2;
        float4* d2 = (float4*)W2s;
        #pragma unroll
        for (int e = t; e < (COUT * COUT) / 4; e += THREADS) d2[e] = s2[e];
    }
    #pragma unroll
    for (int e = t; e < PTS2 * KNB; e += THREADS) {
        int row = e >> 4;
        idxs[e] = (i0 + row < N) ? idx[(size_t)(i0 + row) * KNB + (e & 15)] : 0;
    }
    if (t < PTS2 * 3) {
        int pt = t / 3, d = t - pt * 3;
        if (i0 + pt < N) cs[pt * 3 + d] = coords[(size_t)(i0 + pt) * 3 + d];
    }
    __syncthreads();

    // ---- phase A: gather + packed GELU + mean ------------------------------
    #pragma unroll
    for (int r = 0; r < 2; ++r) {
        const int pl = pg * 2 + r;
        const int i  = i0 + pl;
        float h0 = 0.f, h1 = 0.f, h2 = 0.f, h3 = 0.f;
        if (i < N) {
            const float4* W1v = (const float4*)W1;
            float4 w0 = __ldg(W1v + 0 * 16 + q);
            float4 w1 = __ldg(W1v + 1 * 16 + q);
            float4 w2 = __ldg(W1v + 2 * 16 + q);
            float cx = cs[pl * 3 + 0], cy = cs[pl * 3 + 1], cz = cs[pl * 3 + 2];
            float bx = -(cx * w0.x + cy * w1.x + cz * w2.x);
            float by = -(cx * w0.y + cy * w1.y + cz * w2.y);
            float bz = -(cx * w0.z + cy * w1.z + cz * w2.z);
            float bw = -(cx * w0.w + cy * w1.w + cz * w2.w);
            u64 bLo = pack2(bx, by), bHi = pack2(bz, bw);
            u64 sELo = 0, sEHi = 0;   // sum of |x| * 0.5 erf
            u64 sxLo = 0, sxHi = 0;   // sum of x
            #pragma unroll
            for (int k = 0; k < KNB; ++k) {
                int j = idxs[pl * KNB + k];
                float4 a = *(const float4*)(g_A + (size_t)j * COUT + q * 4);
                u64 xLo = add2(pack2(a.x, a.y), bLo);
                u64 xHi = add2(pack2(a.z, a.w), bHi);
                sxLo = add2(sxLo, xLo);
                sxHi = add2(sxHi, xHi);
                sELo = gelu_acc2(sELo, xLo);
                sEHi = gelu_acc2(sEHi, xHi);
            }
            // h = (0.5*sx + sE) / 16
            u64 hLo = fma2(sxLo, dup2(0.03125f), mul2(sELo, dup2(0.0625f)));
            u64 hHi = fma2(sxHi, dup2(0.03125f), mul2(sEHi, dup2(0.0625f)));
            unpack2(hLo, h0, h1);
            unpack2(hHi, h2, h3);
        }
        hT[(q * 4 + 0) * 36 + pl] = h0;
        hT[(q * 4 + 1) * 36 + pl] = h1;
        hT[(q * 4 + 2) * 36 + pl] = h2;
        hT[(q * 4 + 3) * 36 + pl] = h3;
    }
    __syncthreads();

    // ---- phase B: out += Hbar @ W2 (acc init = skip written by K1b) --------
    u64 accLo[2], accHi[2];
    #pragma unroll
    for (int r = 0; r < 2; ++r) {
        int i = i0 + pg * 2 + r;
        if (i < N) {
            float4 o = *(const float4*)(out + (size_t)i * COUT + q * 4);
            accLo[r] = pack2(o.x, o.y);
            accHi[r] = pack2(o.z, o.w);
        } else {
            accLo[r] = 0; accHi[r] = 0;
        }
    }

    #pragma unroll 8
    for (int j = 0; j < COUT; ++j) {
        float4 wv2 = *(const float4*)(W2s + j * COUT + q * 4);
        u64 w2lo = pack2(wv2.x, wv2.y), w2hi = pack2(wv2.z, wv2.w);
        float2 h2 = *(const float2*)(hT + j * 36 + pg * 2);

        u64 hd;
        hd = pack2(h2.x, h2.x);
        accLo[0] = fma2(hd, w2lo, accLo[0]);  accHi[0] = fma2(hd, w2hi, accHi[0]);
        hd = pack2(h2.y, h2.y);
        accLo[1] = fma2(hd, w2lo, accLo[1]);  accHi[1] = fma2(hd, w2hi, accHi[1]);
    }

    #pragma unroll
    for (int r = 0; r < 2; ++r) {
        int i = i0 + pg * 2 + r;
        if (i < N) {
            float o0, o1, o2, o3;
            unpack2(accLo[r], o0, o1);
            unpack2(accHi[r], o2, o3);
            *(float4*)(out + (size_t)i * COUT + q * 4) = make_float4(o0, o1, o2, o3);
        }
    }
}

// ---------------------------------------------------------------------------
// Launch
// ---------------------------------------------------------------------------
extern "C" void kernel_launch(void* const* d_in, const int* in_sizes, int n_in,
                              void* d_out, int out_size) {
    const float* coords   = (const float*)d_in[0];
    const float* features = (const float*)d_in[1];
    const int*   idx      = (const int*)d_in[2];
    const float* W1       = (const float*)d_in[3];
    const float* b1       = (const float*)d_in[4];
    const float* W2       = (const float*)d_in[5];
    const float* b2       = (const float*)d_in[6];
    const float* Ws       = (const float*)d_in[7];
    const float* bs       = (const float*)d_in[8];
    float*       out      = (float*)d_out;

    const int N = in_sizes[0] / 3;
    const int blocks1 = (N + PTS - 1) / PTS;
    const int blocks2 = (N + PTS2 - 1) / PTS2;

    compute_A_kernel<<<blocks1, THREADS>>>(coords, features, W1, b1, N);
    skip_kernel<<<blocks1, THREADS>>>(features, Ws, b2, bs, out, N);
    fused_main_kernel<<<blocks2, THREADS>>>(coords, idx, W1, W2, out, N);
}

// round 12
// speedup vs baseline: 1.5553x; 1.0332x over previous
#include <cuda_runtime.h>
#include <math.h>

// Problem constants (fixed by the dataset)
#define NMAX   100000
#define CIN    64
#define COUT   64
#define KNB    16
#define DIN    67          // 3 + CIN
#define PTS    64          // points per block (K1 paths)
#define PTS2   32          // points per block (K2)
#define THREADS 256

typedef unsigned long long u64;

// Scratch for per-node A = [coords, feats] @ W1 + b1  (25.6 MB)
__device__ float g_A[(size_t)NMAX * COUT];

// ---- packed f32x2 helpers (sm_100+) --------------------------------------
__device__ __forceinline__ u64 pack2(float lo, float hi) {
    u64 r; asm("mov.b64 %0, {%1, %2};" : "=l"(r) : "f"(lo), "f"(hi)); return r;
}
__device__ __forceinline__ void unpack2(u64 v, float& lo, float& hi) {
    asm("mov.b64 {%0, %1}, %2;" : "=f"(lo), "=f"(hi) : "l"(v));
}
__device__ __forceinline__ u64 fma2(u64 a, u64 b, u64 c) {
    u64 d; asm("fma.rn.f32x2 %0, %1, %2, %3;" : "=l"(d) : "l"(a), "l"(b), "l"(c));
    return d;
}
__device__ __forceinline__ u64 mul2(u64 a, u64 b) {
    u64 d; asm("mul.rn.f32x2 %0, %1, %2;" : "=l"(d) : "l"(a), "l"(b)); return d;
}
__device__ __forceinline__ u64 add2(u64 a, u64 b) {
    u64 d; asm("add.rn.f32x2 %0, %1, %2;" : "=l"(d) : "l"(a), "l"(b)); return d;
}
__device__ __forceinline__ u64 and2(u64 a, u64 b) {
    u64 d; asm("and.b64 %0, %1, %2;" : "=l"(d) : "l"(a), "l"(b)); return d;
}
__device__ __forceinline__ u64 dup2(float f) {
    unsigned u = __float_as_uint(f);
    return (u64)u | ((u64)u << 32);
}
__device__ __forceinline__ float rcpf(float x) {
    float r; asm("rcp.approx.ftz.f32 %0, %1;" : "=f"(r) : "f"(x)); return r;
}

// ---- packed GELU accumulate (2 values) ------------------------------------
// s += |x| * 0.5*erf(|x|/sqrt2); caller handles the 0.5x term via sx.
// erf via A&S 7.1.28, coefficients pre-scaled by (1/sqrt2)^k: |eps|<=3e-7.
__device__ __forceinline__ u64 gelu_acc2(u64 s, u64 x) {
    u64 ax = and2(x, 0x7FFFFFFF7FFFFFFFULL);
    u64 p  = fma2(dup2(0.0000053830f), ax, dup2(0.0000488909f));
    p = fma2(p, ax, dup2(0.0000380036f));
    p = fma2(p, ax, dup2(0.0032776424f));
    p = fma2(p, ax, dup2(0.0211410061f));
    p = fma2(p, ax, dup2(0.0498673400f));
    p = fma2(p, ax, dup2(1.0f));
    float plo, phi; unpack2(p, plo, phi);
    u64 r = pack2(rcpf(plo), rcpf(phi));
    u64 r2  = mul2(r, r);
    u64 r4  = mul2(r2, r2);
    u64 r8  = mul2(r4, r4);
    u64 r16 = mul2(r8, r8);
    u64 Eh  = fma2(r16, dup2(-0.5f), dup2(0.5f));   // 0.5 * erf
    return fma2(ax, Eh, s);
}

// ---------------------------------------------------------------------------
// Kernel 1 (merged): blocks [0, nbA)     : g_A = [c,f]@W1 + b1
//                    blocks [nbA, 2*nbA) : out = f@Ws + (b2+bs)
// Both paths use the proven R9 tiling; smem is a union (max 35.4 KB).
// ---------------------------------------------------------------------------
__global__ __launch_bounds__(THREADS, 4)
void precompute_kernel(const float* __restrict__ coords,
                       const float* __restrict__ features,
                       const float* __restrict__ W1,
                       const float* __restrict__ b1,
                       const float* __restrict__ Ws,
                       const float* __restrict__ b2,
                       const float* __restrict__ bs,
                       float* __restrict__ out,
                       int N, int nbA) {
    __shared__ float smbuf[8844];   // max(4288+67*68, 4096+64*68)

    const int t  = threadIdx.x;
    const int q  = t & 15;
    const int pg = t >> 4;

    if ((int)blockIdx.x < nbA) {
        // ================= path A: g_A = [c,f]@W1 + b1 =================
        float* W1s = smbuf;             // [67][64]
        float* xsT = smbuf + 4288;      // [67][68]
        const int i0 = blockIdx.x * PTS;

        {
            const float4* src = (const float4*)W1;
            float4* dst = (float4*)W1s;
            for (int e = t; e < (DIN * COUT) / 4; e += THREADS) dst[e] = src[e];
        }
        {
            int c  = t & 63;
            int p0 = t >> 6;
            #pragma unroll
            for (int rr = 0; rr < 16; ++rr) {
                int pt = p0 * 16 + rr;
                if (i0 + pt < N)
                    xsT[(3 + c) * 68 + pt] = features[(size_t)(i0 + pt) * CIN + c];
            }
        }
        if (t < PTS * 3) {
            int pt = t / 3, d = t - pt * 3;
            if (i0 + pt < N) xsT[d * 68 + pt] = coords[(size_t)(i0 + pt) * 3 + d];
        }
        __syncthreads();

        u64 accLo[4], accHi[4];
        {
            float4 bb = ((const float4*)b1)[q];
            u64 blo = pack2(bb.x, bb.y), bhi = pack2(bb.z, bb.w);
            #pragma unroll
            for (int r = 0; r < 4; ++r) { accLo[r] = blo; accHi[r] = bhi; }
        }
        #pragma unroll
        for (int j = 0; j < DIN; ++j) {
            float4 w = *(const float4*)(W1s + j * COUT + q * 4);
            u64 wlo = pack2(w.x, w.y), whi = pack2(w.z, w.w);
            float4 xv = *(const float4*)(xsT + j * 68 + pg * 4);
            u64 x0 = pack2(xv.x, xv.x);
            u64 x1 = pack2(xv.y, xv.y);
            u64 x2 = pack2(xv.z, xv.z);
            u64 x3 = pack2(xv.w, xv.w);
            accLo[0] = fma2(x0, wlo, accLo[0]);  accHi[0] = fma2(x0, whi, accHi[0]);
            accLo[1] = fma2(x1, wlo, accLo[1]);  accHi[1] = fma2(x1, whi, accHi[1]);
            accLo[2] = fma2(x2, wlo, accLo[2]);  accHi[2] = fma2(x2, whi, accHi[2]);
            accLo[3] = fma2(x3, wlo, accLo[3]);  accHi[3] = fma2(x3, whi, accHi[3]);
        }
        #pragma unroll
        for (int r = 0; r < 4; ++r) {
            int i = i0 + pg * 4 + r;
            if (i < N) {
                float o0, o1, o2, o3;
                unpack2(accLo[r], o0, o1);
                unpack2(accHi[r], o2, o3);
                *(float4*)(g_A + (size_t)i * COUT + q * 4) = make_float4(o0, o1, o2, o3);
            }
        }
    } else {
        // ================= path B: out = f@Ws + (b2+bs) =================
        float* Wss = smbuf;             // [64][64]
        float* fsT = smbuf + 4096;      // [64][68]
        const int i0 = ((int)blockIdx.x - nbA) * PTS;

        {
            const float4* ss = (const float4*)Ws;
            float4* ds = (float4*)Wss;
            for (int e = t; e < (CIN * COUT) / 4; e += THREADS) ds[e] = ss[e];
        }
        {
            int c  = t & 63;
            int p0 = t >> 6;
            #pragma unroll
            for (int rr = 0; rr < 16; ++rr) {
                int pt = p0 * 16 + rr;
                if (i0 + pt < N)
                    fsT[c * 68 + pt] = features[(size_t)(i0 + pt) * CIN + c];
            }
        }
        __syncthreads();

        u64 accLo[4], accHi[4];
        {
            float4 bb2 = ((const float4*)b2)[q];
            float4 bbs = ((const float4*)bs)[q];
            u64 blo = pack2(bb2.x + bbs.x, bb2.y + bbs.y);
            u64 bhi = pack2(bb2.z + bbs.z, bb2.w + bbs.w);
            #pragma unroll
            for (int r = 0; r < 4; ++r) { accLo[r] = blo; accHi[r] = bhi; }
        }
        #pragma unroll
        for (int j = 0; j < CIN; ++j) {
            float4 w = *(const float4*)(Wss + j * COUT + q * 4);
            u64 wlo = pack2(w.x, w.y), whi = pack2(w.z, w.w);
            float4 xv = *(const float4*)(fsT + j * 68 + pg * 4);
            u64 x0 = pack2(xv.x, xv.x);
            u64 x1 = pack2(xv.y, xv.y);
            u64 x2 = pack2(xv.z, xv.z);
            u64 x3 = pack2(xv.w, xv.w);
            accLo[0] = fma2(x0, wlo, accLo[0]);  accHi[0] = fma2(x0, whi, accHi[0]);
            accLo[1] = fma2(x1, wlo, accLo[1]);  accHi[1] = fma2(x1, whi, accHi[1]);
            accLo[2] = fma2(x2, wlo, accLo[2]);  accHi[2] = fma2(x2, whi, accHi[2]);
            accLo[3] = fma2(x3, wlo, accLo[3]);  accHi[3] = fma2(x3, whi, accHi[3]);
        }
        #pragma unroll
        for (int r = 0; r < 4; ++r) {
            int i = i0 + pg * 4 + r;
            if (i < N) {
                float o0, o1, o2, o3;
                unpack2(accLo[r], o0, o1);
                unpack2(accHi[r], o2, o3);
                *(float4*)(out + (size_t)i * COUT + q * 4) = make_float4(o0, o1, o2, o3);
            }
        }
    }
}

// ---------------------------------------------------------------------------
// Kernel 2: gather + GELU + mean + (out += Hbar @ W2), 32 points / block.
// Thread (pg, q): 2 points x 4 channels, both points interleaved in the
// k-loop with 1-deep prefetch so 2 LDG.128 chains stay in flight.
// occ 4 (reg cap 64) for ILP headroom.  Static smem ~26 KB.
// ---------------------------------------------------------------------------
__global__ __launch_bounds__(THREADS, 4)
void fused_main_kernel(const float* __restrict__ coords,
                       const int* __restrict__ idx,
                       const float* __restrict__ W1,
                       const float* __restrict__ W2,
                       float* __restrict__ out,
                       int N) {
    __shared__ float W2s[COUT * COUT];     // 16 KB
    __shared__ float hT[COUT * 36];        // [channel][point], stride 36
    __shared__ float cs[PTS2 * 3];
    __shared__ int   idxs[PTS2 * KNB];

    const int t  = threadIdx.x;
    const int i0 = blockIdx.x * PTS2;
    const int q  = t & 15;
    const int pg = t >> 4;

    // ---- staging -----------------------------------------------------------
    {
        const float4* s2 = (const float4*)W2;
        float4* d2 = (float4*)W2s;
        #pragma unroll
        for (int e = t; e < (COUT * COUT) / 4; e += THREADS) d2[e] = s2[e];
    }
    #pragma unroll
    for (int e = t; e < PTS2 * KNB; e += THREADS) {
        int row = e >> 4;
        idxs[e] = (i0 + row < N) ? idx[(size_t)(i0 + row) * KNB + (e & 15)] : 0;
    }
    if (t < PTS2 * 3) {
        int pt = t / 3, d = t - pt * 3;
        if (i0 + pt < N) cs[pt * 3 + d] = coords[(size_t)(i0 + pt) * 3 + d];
    }
    __syncthreads();

    // ---- phase A: interleaved 2-point gather + packed GELU + mean ----------
    const int pl0 = pg * 2, pl1 = pl0 + 1;
    {
        const float4* W1v = (const float4*)W1;
        float4 w0 = __ldg(W1v + 0 * 16 + q);
        float4 w1 = __ldg(W1v + 1 * 16 + q);
        float4 w2 = __ldg(W1v + 2 * 16 + q);

        float c0x = cs[pl0 * 3 + 0], c0y = cs[pl0 * 3 + 1], c0z = cs[pl0 * 3 + 2];
        float c1x = cs[pl1 * 3 + 0], c1y = cs[pl1 * 3 + 1], c1z = cs[pl1 * 3 + 2];
        u64 b0Lo = pack2(-(c0x * w0.x + c0y * w1.x + c0z * w2.x),
                         -(c0x * w0.y + c0y * w1.y + c0z * w2.y));
        u64 b0Hi = pack2(-(c0x * w0.z + c0y * w1.z + c0z * w2.z),
                         -(c0x * w0.w + c0y * w1.w + c0z * w2.w));
        u64 b1Lo = pack2(-(c1x * w0.x + c1y * w1.x + c1z * w2.x),
                         -(c1x * w0.y + c1y * w1.y + c1z * w2.y));
        u64 b1Hi = pack2(-(c1x * w0.z + c1y * w1.z + c1z * w2.z),
                         -(c1x * w0.w + c1y * w1.w + c1z * w2.w));

        u64 sE0Lo = 0, sE0Hi = 0, sx0Lo = 0, sx0Hi = 0;
        u64 sE1Lo = 0, sE1Hi = 0, sx1Lo = 0, sx1Hi = 0;

        const float* gAq = g_A + q * 4;
        float4 a0 = *(const float4*)(gAq + (size_t)idxs[pl0 * KNB] * COUT);
        float4 a1 = *(const float4*)(gAq + (size_t)idxs[pl1 * KNB] * COUT);

        #pragma unroll
        for (int k = 0; k < KNB; ++k) {
            float4 n0, n1;
            if (k < KNB - 1) {
                n0 = *(const float4*)(gAq + (size_t)idxs[pl0 * KNB + k + 1] * COUT);
                n1 = *(const float4*)(gAq + (size_t)idxs[pl1 * KNB + k + 1] * COUT);
            }
            u64 x;
            x = add2(pack2(a0.x, a0.y), b0Lo);
            sx0Lo = add2(sx0Lo, x);  sE0Lo = gelu_acc2(sE0Lo, x);
            x = add2(pack2(a0.z, a0.w), b0Hi);
            sx0Hi = add2(sx0Hi, x);  sE0Hi = gelu_acc2(sE0Hi, x);
            x = add2(pack2(a1.x, a1.y), b1Lo);
            sx1Lo = add2(sx1Lo, x);  sE1Lo = gelu_acc2(sE1Lo, x);
            x = add2(pack2(a1.z, a1.w), b1Hi);
            sx1Hi = add2(sx1Hi, x);  sE1Hi = gelu_acc2(sE1Hi, x);
            if (k < KNB - 1) { a0 = n0; a1 = n1; }
        }

        // h = (0.5*sx + sE) / 16
        float h0, h1, h2, h3;
        u64 hLo = fma2(sx0Lo, dup2(0.03125f), mul2(sE0Lo, dup2(0.0625f)));
        u64 hHi = fma2(sx0Hi, dup2(0.03125f), mul2(sE0Hi, dup2(0.0625f)));
        unpack2(hLo, h0, h1);  unpack2(hHi, h2, h3);
        hT[(q * 4 + 0) * 36 + pl0] = h0;
        hT[(q * 4 + 1) * 36 + pl0] = h1;
        hT[(q * 4 + 2) * 36 + pl0] = h2;
        hT[(q * 4 + 3) * 36 + pl0] = h3;
        hLo = fma2(sx1Lo, dup2(0.03125f), mul2(sE1Lo, dup2(0.0625f)));
        hHi = fma2(sx1Hi, dup2(0.03125f), mul2(sE1Hi, dup2(0.0625f)));
        unpack2(hLo, h0, h1);  unpack2(hHi, h2, h3);
        hT[(q * 4 + 0) * 36 + pl1] = h0;
        hT[(q * 4 + 1) * 36 + pl1] = h1;
        hT[(q * 4 + 2) * 36 + pl1] = h2;
        hT[(q * 4 + 3) * 36 + pl1] = h3;
    }
    __syncthreads();

    // ---- phase B: out += Hbar @ W2 (acc init = skip written by K1) ---------
    u64 accLo[2], accHi[2];
    #pragma unroll
    for (int r = 0; r < 2; ++r) {
        int i = i0 + pg * 2 + r;
        if (i < N) {
            float4 o = *(const float4*)(out + (size_t)i * COUT + q * 4);
            accLo[r] = pack2(o.x, o.y);
            accHi[r] = pack2(o.z, o.w);
        } else {
            accLo[r] = 0; accHi[r] = 0;
        }
    }

    #pragma unroll 8
    for (int j = 0; j < COUT; ++j) {
        float4 wv2 = *(const float4*)(W2s + j * COUT + q * 4);
        u64 w2lo = pack2(wv2.x, wv2.y), w2hi = pack2(wv2.z, wv2.w);
        float2 hp = *(const float2*)(hT + j * 36 + pg * 2);

        u64 hd;
        hd = pack2(hp.x, hp.x);
        accLo[0] = fma2(hd, w2lo, accLo[0]);  accHi[0] = fma2(hd, w2hi, accHi[0]);
        hd = pack2(hp.y, hp.y);
        accLo[1] = fma2(hd, w2lo, accLo[1]);  accHi[1] = fma2(hd, w2hi, accHi[1]);
    }

    #pragma unroll
    for (int r = 0; r < 2; ++r) {
        int i = i0 + pg * 2 + r;
        if (i < N) {
            float o0, o1, o2, o3;
            unpack2(accLo[r], o0, o1);
            unpack2(accHi[r], o2, o3);
            *(float4*)(out + (size_t)i * COUT + q * 4) = make_float4(o0, o1, o2, o3);
        }
    }
}

// ---------------------------------------------------------------------------
// Launch
// ---------------------------------------------------------------------------
extern "C" void kernel_launch(void* const* d_in, const int* in_sizes, int n_in,
                              void* d_out, int out_size) {
    const float* coords   = (const float*)d_in[0];
    const float* features = (const float*)d_in[1];
    const int*   idx      = (const int*)d_in[2];
    const float* W1       = (const float*)d_in[3];
    const float* b1       = (const float*)d_in[4];
    const float* W2       = (const float*)d_in[5];
    const float* b2       = (const float*)d_in[6];
    const float* Ws       = (const float*)d_in[7];
    const float* bs       = (const float*)d_in[8];
    float*       out      = (float*)d_out;

    const int N = in_sizes[0] / 3;
    const int nbA = (N + PTS - 1) / PTS;
    const int blocks2 = (N + PTS2 - 1) / PTS2;

    precompute_kernel<<<2 * nbA, THREADS>>>(coords, features, W1, b1, Ws, b2,
                                            bs, out, N, nbA);
    fused_main_kernel<<<blocks2, THREADS>>>(coords, idx, W1, W2, out, N);
}